// round 1
// baseline (speedup 1.0000x reference)
#include <cuda_runtime.h>
#include <cstdint>

// ---------------------------------------------------------------------------
// Octree entropy model:
//   stage1: embed -> conv(relu) -> resnet -> resnet          (N1 nodes, nbr_curr)
//   stage2: parent-gather + octant emb -> conv(relu) -> resnet -> resnet (N2, nbr_next)
//   heads : two 64->64(relu)->16 softmax heads, -log2(p_gt) bits sum / n_points
// ---------------------------------------------------------------------------

#define NMAX 81920
#define KNB  27
#define KCC  (27 * 64 * 64)
#define TM   128
#define SSTR 65
#define HB   592   // heads grid

__device__ float g_bufA[NMAX * 64];
__device__ float g_bufB[NMAX * 64];
__device__ float g_bufC[NMAX * 64];
__device__ float g_partials[1024];

// ---------------- embed: f[i] = prior_emb[occ[i]] ----------------
__global__ void embed_kernel(const float* __restrict__ emb, const int* __restrict__ occ,
                             float* __restrict__ out, int N) {
    int i = blockIdx.x * 256 + threadIdx.x;
    if (i < N * 64) out[i] = emb[occ[i >> 6] * 64 + (i & 63)];
}

// ---------------- g init: g[i] = f[parent[i]] + temb8[oct[i]] ----------------
__global__ void ginit_kernel(const float* __restrict__ f, const int* __restrict__ parent,
                             const float* __restrict__ temb, const int* __restrict__ oct,
                             float* __restrict__ out, int N) {
    int i = blockIdx.x * 256 + threadIdx.x;
    if (i < N * 64) {
        int node = i >> 6, c = i & 63;
        out[i] = f[(size_t)parent[node] * 64 + c] + temb[oct[node] * 64 + c];
    }
}

// ---------------- sparse conv: out[r,:] = epilogue( sum_k in[nbr[r,k],:] @ W[k] ) ---
// mode 0: relu(acc)      mode 1: relu(res + acc)
__global__ __launch_bounds__(128, 4) void spconv_kernel(
    const float* __restrict__ in, const int* __restrict__ nbr,
    const float* __restrict__ W, const float* __restrict__ res,
    float* __restrict__ out, int N, int mode)
{
    extern __shared__ float smem[];
    float* sIn = smem;                 // TM * SSTR  (row-major, stride 65 -> bank (r+j)%32)
    float* sW  = smem + TM * SSTR;     // 64 * 64

    const int t    = threadIdx.x;
    const int row0 = blockIdx.x * TM;

    unsigned long long acc[32];        // 32 packed f32x2 pairs = 64 output channels
#pragma unroll
    for (int i = 0; i < 32; i++) acc[i] = 0ull;

    const int grr = t >> 2;            // gather: 4 threads per row
    const int cs  = (t & 3) * 16;

    for (int k = 0; k < KNB; k++) {
        __syncthreads();
        // stage W[k] -> smem (coalesced float4)
        const float4* Wk  = (const float4*)(W + k * 4096);
        float4*       sW4 = (float4*)sW;
#pragma unroll
        for (int i = 0; i < 8; i++) sW4[t + i * 128] = Wk[t + i * 128];

        // gather 128 rows of the input (zeros where nbr == -1 or row >= N)
#pragma unroll
        for (int pass = 0; pass < 4; pass++) {
            int lr  = grr + pass * 32;
            int gr  = row0 + lr;
            int idx = (gr < N) ? nbr[gr * KNB + k] : -1;
            float* dst = sIn + lr * SSTR + cs;
            if (idx >= 0) {
                const float4* src = (const float4*)(in + (size_t)idx * 64 + cs);
#pragma unroll
                for (int q = 0; q < 4; q++) {
                    float4 v = src[q];
                    dst[q * 4 + 0] = v.x; dst[q * 4 + 1] = v.y;
                    dst[q * 4 + 2] = v.z; dst[q * 4 + 3] = v.w;
                }
            } else {
#pragma unroll
                for (int q = 0; q < 16; q++) dst[q] = 0.f;
            }
        }
        __syncthreads();

        // compute: this thread owns row t; rank-1 update over j with FFMA2
        const float* aRow = sIn + t * SSTR;
#pragma unroll 2
        for (int j = 0; j < 64; j++) {
            float a = aRow[j];
            unsigned long long a2;
            asm("mov.b64 %0, {%1, %1};" : "=l"(a2) : "f"(a));
            const ulonglong2* bp = (const ulonglong2*)(sW + j * 64);
#pragma unroll
            for (int p = 0; p < 16; p++) {
                ulonglong2 b = bp[p];
                asm("fma.rn.f32x2 %0, %1, %2, %0;" : "+l"(acc[2 * p])     : "l"(a2), "l"(b.x));
                asm("fma.rn.f32x2 %0, %1, %2, %0;" : "+l"(acc[2 * p + 1]) : "l"(a2), "l"(b.y));
            }
        }
    }

    int r = row0 + t;
    if (r < N) {
        float*       o  = out + (size_t)r * 64;
        const float* rs = (mode == 1) ? (res + (size_t)r * 64) : nullptr;
#pragma unroll
        for (int p = 0; p < 32; p++) {
            float x0, x1;
            asm("mov.b64 {%0, %1}, %2;" : "=f"(x0), "=f"(x1) : "l"(acc[p]));
            if (mode == 1) { x0 += rs[2 * p]; x1 += rs[2 * p + 1]; }
            o[2 * p]     = fmaxf(x0, 0.f);
            o[2 * p + 1] = fmaxf(x1, 0.f);
        }
    }
}

// ---------------- heads ----------------
// One warp per node. lane holds channels {lane, lane+32}.
__device__ __forceinline__ float head_eval(
    float x0, float x1, const float* __restrict__ Wa, const float* __restrict__ Wb,
    const float* __restrict__ ba, const float* __restrict__ bb, int lane, int cls)
{
    float t0 = ba[lane], t1 = ba[32 + lane];
#pragma unroll
    for (int j = 0; j < 32; j++) {
        float xj = __shfl_sync(0xffffffffu, x0, j);
        t0 = fmaf(xj, Wa[j * 64 + lane], t0);
        t1 = fmaf(xj, Wa[j * 64 + 32 + lane], t1);
    }
#pragma unroll
    for (int j = 0; j < 32; j++) {
        float xj = __shfl_sync(0xffffffffu, x1, j);
        t0 = fmaf(xj, Wa[(j + 32) * 64 + lane], t0);
        t1 = fmaf(xj, Wa[(j + 32) * 64 + 32 + lane], t1);
    }
    t0 = fmaxf(t0, 0.f); t1 = fmaxf(t1, 0.f);

    float l = (lane < 16) ? bb[lane] : -1e30f;
#pragma unroll
    for (int j = 0; j < 32; j++) {
        float u0 = __shfl_sync(0xffffffffu, t0, j);
        float u1 = __shfl_sync(0xffffffffu, t1, j);
        if (lane < 16) {
            l = fmaf(u0, Wb[j * 16 + lane], l);
            l = fmaf(u1, Wb[(j + 32) * 16 + lane], l);
        }
    }
    // softmax over lanes 0..15 (xor offsets stay within the 16-group)
    float m = l;
#pragma unroll
    for (int off = 8; off; off >>= 1) m = fmaxf(m, __shfl_xor_sync(0xffffffffu, m, off));
    float e = (lane < 16) ? expf(l - m) : 0.f;
    float s = e;
#pragma unroll
    for (int off = 8; off; off >>= 1) s += __shfl_xor_sync(0xffffffffu, s, off);
    float egt  = __shfl_sync(0xffffffffu, e, cls);
    float sgt  = __shfl_sync(0xffffffffu, s, 0);
    float term = -log2f(egt / sgt + 1e-10f);
    term = fminf(fmaxf(term, 0.f), 50.f);
    return (lane == 0) ? term : 0.f;
}

__global__ __launch_bounds__(256) void heads_kernel(
    const float* __restrict__ g, const int* __restrict__ next_occ,
    const float* __restrict__ W0a, const float* __restrict__ b0a,
    const float* __restrict__ W0b, const float* __restrict__ b0b,
    const float* __restrict__ W1a, const float* __restrict__ b1a,
    const float* __restrict__ W1b, const float* __restrict__ b1b,
    const float* __restrict__ s1, float* __restrict__ partials, int N)
{
    __shared__ float sW0a[4096], sW1a[4096], sW0b[1024], sW1b[1024], sS1[1024];
    __shared__ float sB[160];
    __shared__ float warpsum[8];
    int t = threadIdx.x;
    for (int i = t; i < 4096; i += 256) { sW0a[i] = W0a[i]; sW1a[i] = W1a[i]; }
    for (int i = t; i < 1024; i += 256) { sW0b[i] = W0b[i]; sW1b[i] = W1b[i]; sS1[i] = s1[i]; }
    if (t < 64) { sB[t] = b0a[t]; sB[80 + t] = b1a[t]; }
    if (t < 16) { sB[64 + t] = b0b[t]; sB[144 + t] = b1b[t]; }
    __syncthreads();

    int lane = t & 31, w = t >> 5;
    int warpG = blockIdx.x * 8 + w;
    int nW    = gridDim.x * 8;
    float bits = 0.f;
    for (int node = warpG; node < N; node += nW) {
        float g0 = g[(size_t)node * 64 + lane];
        float g1 = g[(size_t)node * 64 + 32 + lane];
        int occ   = next_occ[node];
        int lower = occ & 15, upper = (occ >> 4) & 15;
        bits += head_eval(g0, g1, sW0a, sW0b, sB, sB + 64, lane, lower);
        float h0 = g0 + sS1[lower * 64 + lane];
        float h1 = g1 + sS1[lower * 64 + 32 + lane];
        bits += head_eval(h0, h1, sW1a, sW1b, sB + 80, sB + 144, lane, upper);
    }
    if (lane == 0) warpsum[w] = bits;
    __syncthreads();
    if (t == 0) {
        float v = 0.f;
#pragma unroll
        for (int i = 0; i < 8; i++) v += warpsum[i];
        partials[blockIdx.x] = v;
    }
}

__global__ void finalize_kernel(const float* __restrict__ partials, int nb,
                                const int* __restrict__ npts, float* __restrict__ out) {
    __shared__ float s[256];
    float v = 0.f;
    for (int i = threadIdx.x; i < nb; i += 256) v += partials[i];
    s[threadIdx.x] = v; __syncthreads();
    for (int st = 128; st; st >>= 1) {
        if (threadIdx.x < st) s[threadIdx.x] += s[threadIdx.x + st];
        __syncthreads();
    }
    if (threadIdx.x == 0) out[0] = s[0] / (float)npts[0];
}

// ---------------------------------------------------------------------------
extern "C" void kernel_launch(void* const* d_in, const int* in_sizes, int n_in,
                              void* d_out, int out_size)
{
    const float* prior = (const float*)d_in[0];
    const float* temb  = (const float*)d_in[1];
    const float* Wp    = (const float*)d_in[2];
    const float* Wt    = (const float*)d_in[3];
    const float* W0a   = (const float*)d_in[4];
    const float* b0a   = (const float*)d_in[5];
    const float* W0b   = (const float*)d_in[6];
    const float* b0b   = (const float*)d_in[7];
    const float* W1a   = (const float*)d_in[8];
    const float* b1a   = (const float*)d_in[9];
    const float* W1b   = (const float*)d_in[10];
    const float* b1b   = (const float*)d_in[11];
    const float* s1    = (const float*)d_in[12];
    const int* curr_occ = (const int*)d_in[13];
    const int* next_occ = (const int*)d_in[14];
    const int* next_oct = (const int*)d_in[15];
    const int* parent   = (const int*)d_in[16];
    const int* nbr1     = (const int*)d_in[17];
    const int* nbr2     = (const int*)d_in[18];
    const int* npts     = (const int*)d_in[19];

    const int N1 = in_sizes[13];
    const int N2 = in_sizes[14];

    float *bA, *bB, *bC, *parts;
    cudaGetSymbolAddress((void**)&bA, g_bufA);
    cudaGetSymbolAddress((void**)&bB, g_bufB);
    cudaGetSymbolAddress((void**)&bC, g_bufC);
    cudaGetSymbolAddress((void**)&parts, g_partials);

    const int SPCONV_SMEM = (TM * SSTR + 4096) * sizeof(float);  // 49,664 B
    cudaFuncSetAttribute(spconv_kernel, cudaFuncAttributeMaxDynamicSharedMemorySize, SPCONV_SMEM);

    const int g1 = (N1 + TM - 1) / TM;
    const int g2 = (N2 + TM - 1) / TM;
    float* output = (float*)d_out;

    // ---- stage 1 (N1, nbr_curr, Wp) ----
    embed_kernel<<<(N1 * 64 + 255) / 256, 256>>>(prior, curr_occ, bA, N1);
    spconv_kernel<<<g1, 128, SPCONV_SMEM>>>(bA, nbr1, Wp + 0 * KCC, nullptr, bB, N1, 0);
    spconv_kernel<<<g1, 128, SPCONV_SMEM>>>(bB, nbr1, Wp + 1 * KCC, nullptr, bC, N1, 0);
    spconv_kernel<<<g1, 128, SPCONV_SMEM>>>(bC, nbr1, Wp + 2 * KCC, bB,      bA, N1, 1);
    spconv_kernel<<<g1, 128, SPCONV_SMEM>>>(bA, nbr1, Wp + 3 * KCC, nullptr, bC, N1, 0);
    spconv_kernel<<<g1, 128, SPCONV_SMEM>>>(bC, nbr1, Wp + 4 * KCC, bA,      bB, N1, 1);

    // ---- stage 2 (N2, nbr_next, Wt) ----
    ginit_kernel<<<(N2 * 64 + 255) / 256, 256>>>(bB, parent, temb, next_oct, bA, N2);
    spconv_kernel<<<g2, 128, SPCONV_SMEM>>>(bA, nbr2, Wt + 0 * KCC, nullptr, bB, N2, 0);
    spconv_kernel<<<g2, 128, SPCONV_SMEM>>>(bB, nbr2, Wt + 1 * KCC, nullptr, bC, N2, 0);
    spconv_kernel<<<g2, 128, SPCONV_SMEM>>>(bC, nbr2, Wt + 2 * KCC, bB,      bA, N2, 1);
    spconv_kernel<<<g2, 128, SPCONV_SMEM>>>(bA, nbr2, Wt + 3 * KCC, nullptr, bC, N2, 0);
    spconv_kernel<<<g2, 128, SPCONV_SMEM>>>(bC, nbr2, Wt + 4 * KCC, bA,      bB, N2, 1);

    // ---- heads + reduction ----
    heads_kernel<<<HB, 256>>>(bB, next_occ, W0a, b0a, W0b, b0b,
                              W1a, b1a, W1b, b1b, s1, parts, N2);
    finalize_kernel<<<1, 256>>>(parts, HB, npts, output);
}

// round 10
// speedup vs baseline: 1.3935x; 1.3935x over previous
#include <cuda_runtime.h>
#include <cstdint>

// ---------------------------------------------------------------------------
// Octree entropy model:
//   stage1: embed -> conv(relu) -> resnet -> resnet          (N1 nodes, nbr_curr)
//   stage2: parent-gather + octant emb -> conv(relu) -> resnet -> resnet (N2, nbr_next)
//   heads : two 64->64(relu)->16 softmax heads, -log2(p_gt) bits sum / n_points
// ---------------------------------------------------------------------------

#define NMAX 81920
#define KNB  27
#define KCC  (27 * 64 * 64)
#define SSTR 68            // smem row stride (== 4 mod 32 -> conflict-free f4 reads)
#define HB   592           // heads grid

__device__ float g_bufA[NMAX * 64];
__device__ float g_bufB[NMAX * 64];
__device__ float g_bufC[NMAX * 64];
__device__ float g_partials[1024];

// ---------------- embed: f[i] = prior_emb[occ[i]] ----------------
__global__ void embed_kernel(const float* __restrict__ emb, const int* __restrict__ occ,
                             float* __restrict__ out, int N) {
    int i = blockIdx.x * 256 + threadIdx.x;
    if (i < N * 64) out[i] = emb[occ[i >> 6] * 64 + (i & 63)];
}

// ---------------- g init: g[i] = f[parent[i]] + temb8[oct[i]] ----------------
__global__ void ginit_kernel(const float* __restrict__ f, const int* __restrict__ parent,
                             const float* __restrict__ temb, const int* __restrict__ oct,
                             float* __restrict__ out, int N) {
    int i = blockIdx.x * 256 + threadIdx.x;
    if (i < N * 64) {
        int node = i >> 6, c = i & 63;
        out[i] = f[(size_t)parent[node] * 64 + c] + temb[oct[node] * 64 + c];
    }
}

// ---------------- sparse conv ----------------
// out[r,:] = epilogue( sum_k in[nbr[r,k],:] @ W[k] ), mode 0: relu, mode 1: relu(res+acc)
// 256 threads. Thread layout: cq = t>>6 (channel quarter, 16 ch, warp-uniform),
// r6 = t&63. Thread computes rows {r6 + 64*i, i<R} x 16 channels.
// TM = 64*R rows per block.
#define FMA2(ACC, A2, B) asm("fma.rn.f32x2 %0, %1, %2, %0;" : "+l"(ACC) : "l"(A2), "l"(B))

template<int R>
__global__ __launch_bounds__(256, 2) void spconv_kernel(
    const float* __restrict__ in, const int* __restrict__ nbr,
    const float* __restrict__ W, const float* __restrict__ res,
    float* __restrict__ out, int N, int mode)
{
    constexpr int TM = 64 * R;
    extern __shared__ unsigned char smem_raw[];
    float* sIn = (float*)smem_raw;          // TM * SSTR
    float* sW  = sIn + TM * SSTR;           // 64 * 64

    const int t    = threadIdx.x;
    const int cq   = t >> 6;                // 0..3, constant per warp
    const int r6   = t & 63;
    const int row0 = blockIdx.x * TM;

    unsigned long long acc[R][8];           // R rows x 16 channels (8 f32x2)
#pragma unroll
    for (int i = 0; i < R; i++)
#pragma unroll
        for (int p = 0; p < 8; p++) acc[i][p] = 0ull;

    for (int k = 0; k < KNB; k++) {
        __syncthreads();
        // stage W[k] -> smem (coalesced float4)
        {
            const float4* Wk4 = (const float4*)(W + k * 4096);
            float4*       sW4 = (float4*)sW;
#pragma unroll
            for (int i = 0; i < 4; i++) sW4[t + i * 256] = Wk4[t + i * 256];
        }
        // gather TM rows x 64 ch, 16-float segments (4 per row)
#pragma unroll
        for (int s = t; s < TM * 4; s += 256) {
            int lr = s >> 2, q = s & 3;
            int gr = row0 + lr;
            int idx = (gr < N) ? __ldg(nbr + gr * KNB + k) : -1;
            float4* dst = (float4*)(sIn + lr * SSTR + q * 16);
            if (idx >= 0) {
                const float4* src = (const float4*)(in + (size_t)idx * 64 + q * 16);
                dst[0] = src[0]; dst[1] = src[1]; dst[2] = src[2]; dst[3] = src[3];
            } else {
                float4 z = make_float4(0.f, 0.f, 0.f, 0.f);
                dst[0] = z; dst[1] = z; dst[2] = z; dst[3] = z;
            }
        }
        __syncthreads();

        // compute
        const float* sWq = sW + cq * 16;
#pragma unroll 2
        for (int j4 = 0; j4 < 64; j4 += 4) {
            float4 a4[R];
#pragma unroll
            for (int i = 0; i < R; i++)
                a4[i] = *(const float4*)(sIn + (r6 + 64 * i) * SSTR + j4);
#pragma unroll
            for (int jj = 0; jj < 4; jj++) {
                const ulonglong2* wp = (const ulonglong2*)(sWq + (j4 + jj) * 64);
                ulonglong2 w0 = wp[0], w1 = wp[1];
#pragma unroll
                for (int i = 0; i < R; i++) {
                    float aj = (jj == 0) ? a4[i].x : (jj == 1) ? a4[i].y
                             : (jj == 2) ? a4[i].z : a4[i].w;
                    unsigned long long a2;
                    asm("mov.b64 %0, {%1, %1};" : "=l"(a2) : "f"(aj));
                    FMA2(acc[i][0], a2, w0.x);
                    FMA2(acc[i][1], a2, w0.y);
                    FMA2(acc[i][2], a2, w1.x);
                    FMA2(acc[i][3], a2, w1.y);
                    FMA2(acc[i][4], a2, wp[2].x);
                    FMA2(acc[i][5], a2, wp[2].y);
                    FMA2(acc[i][6], a2, wp[3].x);
                    FMA2(acc[i][7], a2, wp[3].y);
                }
            }
        }
    }

    // epilogue
#pragma unroll
    for (int i = 0; i < R; i++) {
        int r = row0 + r6 + 64 * i;
        if (r < N) {
            float* o = out + (size_t)r * 64 + cq * 16;
            float x[16];
#pragma unroll
            for (int p = 0; p < 8; p++)
                asm("mov.b64 {%0, %1}, %2;" : "=f"(x[2 * p]), "=f"(x[2 * p + 1]) : "l"(acc[i][p]));
            if (mode == 1) {
                const float* rs = res + (size_t)r * 64 + cq * 16;
#pragma unroll
                for (int p = 0; p < 16; p++) x[p] += rs[p];
            }
#pragma unroll
            for (int q = 0; q < 4; q++) {
                float4 v = make_float4(fmaxf(x[4 * q], 0.f),     fmaxf(x[4 * q + 1], 0.f),
                                       fmaxf(x[4 * q + 2], 0.f), fmaxf(x[4 * q + 3], 0.f));
                ((float4*)o)[q] = v;
            }
        }
    }
}

// ---------------- heads ----------------
// One warp per node. lane holds channels {lane, lane+32}.
__device__ __forceinline__ float head_eval(
    float x0, float x1, const float* __restrict__ Wa, const float* __restrict__ Wb,
    const float* __restrict__ ba, const float* __restrict__ bb, int lane, int cls)
{
    float t0 = ba[lane], t1 = ba[32 + lane];
#pragma unroll
    for (int j = 0; j < 32; j++) {
        float xj = __shfl_sync(0xffffffffu, x0, j);
        t0 = fmaf(xj, Wa[j * 64 + lane], t0);
        t1 = fmaf(xj, Wa[j * 64 + 32 + lane], t1);
    }
#pragma unroll
    for (int j = 0; j < 32; j++) {
        float xj = __shfl_sync(0xffffffffu, x1, j);
        t0 = fmaf(xj, Wa[(j + 32) * 64 + lane], t0);
        t1 = fmaf(xj, Wa[(j + 32) * 64 + 32 + lane], t1);
    }
    t0 = fmaxf(t0, 0.f); t1 = fmaxf(t1, 0.f);

    float l = (lane < 16) ? bb[lane] : -1e30f;
#pragma unroll
    for (int j = 0; j < 32; j++) {
        float u0 = __shfl_sync(0xffffffffu, t0, j);
        float u1 = __shfl_sync(0xffffffffu, t1, j);
        if (lane < 16) {
            l = fmaf(u0, Wb[j * 16 + lane], l);
            l = fmaf(u1, Wb[(j + 32) * 16 + lane], l);
        }
    }
    float m = l;
#pragma unroll
    for (int off = 8; off; off >>= 1) m = fmaxf(m, __shfl_xor_sync(0xffffffffu, m, off));
    float e = (lane < 16) ? expf(l - m) : 0.f;
    float s = e;
#pragma unroll
    for (int off = 8; off; off >>= 1) s += __shfl_xor_sync(0xffffffffu, s, off);
    float egt  = __shfl_sync(0xffffffffu, e, cls);
    float sgt  = __shfl_sync(0xffffffffu, s, 0);
    float term = -log2f(egt / sgt + 1e-10f);
    term = fminf(fmaxf(term, 0.f), 50.f);
    return (lane == 0) ? term : 0.f;
}

__global__ __launch_bounds__(256) void heads_kernel(
    const float* __restrict__ g, const int* __restrict__ next_occ,
    const float* __restrict__ W0a, const float* __restrict__ b0a,
    const float* __restrict__ W0b, const float* __restrict__ b0b,
    const float* __restrict__ W1a, const float* __restrict__ b1a,
    const float* __restrict__ W1b, const float* __restrict__ b1b,
    const float* __restrict__ s1, float* __restrict__ partials, int N)
{
    __shared__ float sW0a[4096], sW1a[4096], sW0b[1024], sW1b[1024], sS1[1024];
    __shared__ float sB[160];
    __shared__ float warpsum[8];
    int t = threadIdx.x;
    for (int i = t; i < 4096; i += 256) { sW0a[i] = W0a[i]; sW1a[i] = W1a[i]; }
    for (int i = t; i < 1024; i += 256) { sW0b[i] = W0b[i]; sW1b[i] = W1b[i]; sS1[i] = s1[i]; }
    if (t < 64) { sB[t] = b0a[t]; sB[80 + t] = b1a[t]; }
    if (t < 16) { sB[64 + t] = b0b[t]; sB[144 + t] = b1b[t]; }
    __syncthreads();

    int lane = t & 31, w = t >> 5;
    int warpG = blockIdx.x * 8 + w;
    int nW    = gridDim.x * 8;
    float bits = 0.f;
    for (int node = warpG; node < N; node += nW) {
        float g0 = g[(size_t)node * 64 + lane];
        float g1 = g[(size_t)node * 64 + 32 + lane];
        int occ   = next_occ[node];
        int lower = occ & 15, upper = (occ >> 4) & 15;
        bits += head_eval(g0, g1, sW0a, sW0b, sB, sB + 64, lane, lower);
        float h0 = g0 + sS1[lower * 64 + lane];
        float h1 = g1 + sS1[lower * 64 + 32 + lane];
        bits += head_eval(h0, h1, sW1a, sW1b, sB + 80, sB + 144, lane, upper);
    }
    if (lane == 0) warpsum[w] = bits;
    __syncthreads();
    if (t == 0) {
        float v = 0.f;
#pragma unroll
        for (int i = 0; i < 8; i++) v += warpsum[i];
        partials[blockIdx.x] = v;
    }
}

__global__ void finalize_kernel(const float* __restrict__ partials, int nb,
                                const int* __restrict__ npts, float* __restrict__ out) {
    __shared__ float s[256];
    float v = 0.f;
    for (int i = threadIdx.x; i < nb; i += 256) v += partials[i];
    s[threadIdx.x] = v; __syncthreads();
    for (int st = 128; st; st >>= 1) {
        if (threadIdx.x < st) s[threadIdx.x] += s[threadIdx.x + st];
        __syncthreads();
    }
    if (threadIdx.x == 0) out[0] = s[0] / (float)npts[0];
}

// ---------------------------------------------------------------------------
extern "C" void kernel_launch(void* const* d_in, const int* in_sizes, int n_in,
                              void* d_out, int out_size)
{
    const float* prior = (const float*)d_in[0];
    const float* temb  = (const float*)d_in[1];
    const float* Wp    = (const float*)d_in[2];
    const float* Wt    = (const float*)d_in[3];
    const float* W0a   = (const float*)d_in[4];
    const float* b0a   = (const float*)d_in[5];
    const float* W0b   = (const float*)d_in[6];
    const float* b0b   = (const float*)d_in[7];
    const float* W1a   = (const float*)d_in[8];
    const float* b1a   = (const float*)d_in[9];
    const float* W1b   = (const float*)d_in[10];
    const float* b1b   = (const float*)d_in[11];
    const float* s1    = (const float*)d_in[12];
    const int* curr_occ = (const int*)d_in[13];
    const int* next_occ = (const int*)d_in[14];
    const int* next_oct = (const int*)d_in[15];
    const int* parent   = (const int*)d_in[16];
    const int* nbr1     = (const int*)d_in[17];
    const int* nbr2     = (const int*)d_in[18];
    const int* npts     = (const int*)d_in[19];

    const int N1 = in_sizes[13];
    const int N2 = in_sizes[14];

    float *bA, *bB, *bC, *parts;
    cudaGetSymbolAddress((void**)&bA, g_bufA);
    cudaGetSymbolAddress((void**)&bB, g_bufB);
    cudaGetSymbolAddress((void**)&bC, g_bufC);
    cudaGetSymbolAddress((void**)&parts, g_partials);

    const int SM1 = (64  * SSTR + 4096) * sizeof(float);   // 33,792 B
    const int SM2 = (128 * SSTR + 4096) * sizeof(float);   // 51,200 B
    cudaFuncSetAttribute(spconv_kernel<1>, cudaFuncAttributeMaxDynamicSharedMemorySize, SM1);
    cudaFuncSetAttribute(spconv_kernel<2>, cudaFuncAttributeMaxDynamicSharedMemorySize, SM2);

    const int g1 = (N1 + 63) / 64;
    const int g2 = (N2 + 127) / 128;
    float* output = (float*)d_out;

    // ---- stage 1 (N1, nbr_curr, Wp) ----
    embed_kernel<<<(N1 * 64 + 255) / 256, 256>>>(prior, curr_occ, bA, N1);
    spconv_kernel<1><<<g1, 256, SM1>>>(bA, nbr1, Wp + 0 * KCC, nullptr, bB, N1, 0);
    spconv_kernel<1><<<g1, 256, SM1>>>(bB, nbr1, Wp + 1 * KCC, nullptr, bC, N1, 0);
    spconv_kernel<1><<<g1, 256, SM1>>>(bC, nbr1, Wp + 2 * KCC, bB,      bA, N1, 1);
    spconv_kernel<1><<<g1, 256, SM1>>>(bA, nbr1, Wp + 3 * KCC, nullptr, bC, N1, 0);
    spconv_kernel<1><<<g1, 256, SM1>>>(bC, nbr1, Wp + 4 * KCC, bA,      bB, N1, 1);

    // ---- stage 2 (N2, nbr_next, Wt) ----
    ginit_kernel<<<(N2 * 64 + 255) / 256, 256>>>(bB, parent, temb, next_oct, bA, N2);
    spconv_kernel<2><<<g2, 256, SM2>>>(bA, nbr2, Wt + 0 * KCC, nullptr, bB, N2, 0);
    spconv_kernel<2><<<g2, 256, SM2>>>(bB, nbr2, Wt + 1 * KCC, nullptr, bC, N2, 0);
    spconv_kernel<2><<<g2, 256, SM2>>>(bC, nbr2, Wt + 2 * KCC, bB,      bA, N2, 1);
    spconv_kernel<2><<<g2, 256, SM2>>>(bA, nbr2, Wt + 3 * KCC, nullptr, bC, N2, 0);
    spconv_kernel<2><<<g2, 256, SM2>>>(bC, nbr2, Wt + 4 * KCC, bA,      bB, N2, 1);

    // ---- heads + reduction ----
    heads_kernel<<<HB, 256>>>(bB, next_occ, W0a, b0a, W0b, b0b,
                              W1a, b1a, W1b, b1b, s1, parts, N2);
    finalize_kernel<<<1, 256>>>(parts, HB, npts, output);
}